// round 1
// baseline (speedup 1.0000x reference)
#include <cuda_runtime.h>
#include <math.h>

// Problem constants (fixed by the dataset; sizes re-derived defensively at launch)
#define NN 50000
#define EE 800000
#define DD 128

// ---------------- scratch (device globals: allocation-free rule) ----------------
__device__ int   g_deg[NN];
__device__ int   g_rowptr[NN + 1];
__device__ int   g_cursor[NN];
__device__ int   g_cols[EE];
__device__ float g_wts[EE];
__device__ float g_dis[NN];
__device__ __align__(16) float g_h[NN * DD];
__device__ __align__(16) float g_agg[NN * DD];
__device__ __align__(16) float g_x[NN * DD];
__device__ float g_stats[2 * DD];   // [0..127]=sum, [128..255]=sumsq
__device__ __align__(16) float g_scale[DD];
__device__ __align__(16) float g_shift[DD];

// ---------------- CSR build ----------------
__global__ void zero_kernel(int n) {
    int i = blockIdx.x * blockDim.x + threadIdx.x;
    for (int j = i; j < n; j += gridDim.x * blockDim.x) g_deg[j] = 0;
    if (i < 2 * DD) g_stats[i] = 0.0f;
}

__global__ void degree_kernel(const int* __restrict__ dst, int e) {
    int i = blockIdx.x * blockDim.x + threadIdx.x;
    if (i < e) atomicAdd(&g_deg[dst[i]], 1);
}

// Single-block scan: exclusive prefix over degrees -> rowptr/cursor; also dis = rsqrt(deg+1)
__global__ void scan_kernel(int n) {
    __shared__ int warp_off[32];
    __shared__ int btot;
    __shared__ int carry;
    int tid = threadIdx.x;
    int lane = tid & 31, wid = tid >> 5;
    if (tid == 0) carry = 0;
    __syncthreads();
    for (int base = 0; base < n; base += 1024) {
        int i = base + tid;
        int v = (i < n) ? g_deg[i] : 0;
        if (i < n) g_dis[i] = rsqrtf((float)v + 1.0f);
        // warp inclusive scan
        int incl = v;
        #pragma unroll
        for (int off = 1; off < 32; off <<= 1) {
            int t = __shfl_up_sync(0xffffffffu, incl, off);
            if (lane >= off) incl += t;
        }
        if (lane == 31) warp_off[wid] = incl;
        __syncthreads();
        if (wid == 0) {
            int w = warp_off[lane];
            int s = w;
            #pragma unroll
            for (int off = 1; off < 32; off <<= 1) {
                int t = __shfl_up_sync(0xffffffffu, s, off);
                if (lane >= off) s += t;
            }
            warp_off[lane] = s - w;
            if (lane == 31) btot = s;
        }
        __syncthreads();
        int excl = incl - v + warp_off[wid] + carry;
        if (i < n) { g_rowptr[i] = excl; g_cursor[i] = excl; }
        __syncthreads();
        if (tid == 0) carry += btot;
        __syncthreads();
    }
    if (tid == 0) g_rowptr[n] = carry;
}

__global__ void fill_kernel(const int* __restrict__ src, const int* __restrict__ dst, int e) {
    int i = blockIdx.x * blockDim.x + threadIdx.x;
    if (i < e) {
        int s = src[i], d = dst[i];
        int pos = atomicAdd(&g_cursor[d], 1);
        g_cols[pos] = s;
        g_wts[pos] = g_dis[s] * g_dis[d];
    }
}

// ---------------- GEMM: h = X @ W  (X: n x 128, W: 128 x 128) ----------------
// block = 256 threads, tile 64 rows x 128 cols, K chunked by 32
__global__ __launch_bounds__(256) void gemm_kernel(const float* __restrict__ Xext,
                                                   const float* __restrict__ W,
                                                   int n, int use_global) {
    __shared__ __align__(16) float xs[64][32];
    __shared__ __align__(16) float ws[32][128];
    const float* X = use_global ? g_x : Xext;
    int tid = threadIdx.x;
    int tx = tid & 31, ty = tid >> 5;
    int m0 = blockIdx.x * 64;

    float4 acc[8];
    #pragma unroll
    for (int j = 0; j < 8; j++) acc[j] = make_float4(0.f, 0.f, 0.f, 0.f);

    for (int kc = 0; kc < 128; kc += 32) {
        #pragma unroll
        for (int i = 0; i < 8; i++) {
            int lin = tid + 256 * i;
            int r = lin >> 5, c = lin & 31;
            int row = m0 + r;
            xs[r][c] = (row < n) ? X[row * 128 + kc + c] : 0.0f;
        }
        #pragma unroll
        for (int i = 0; i < 16; i++) {
            int lin = tid + 256 * i;
            int r = lin >> 7, c = lin & 127;
            ws[r][c] = W[(kc + r) * 128 + c];
        }
        __syncthreads();
        #pragma unroll
        for (int k = 0; k < 32; k++) {
            float4 wv = *(const float4*)&ws[k][tx * 4];
            #pragma unroll
            for (int j = 0; j < 8; j++) {
                float xv = xs[ty * 8 + j][k];
                acc[j].x += xv * wv.x;
                acc[j].y += xv * wv.y;
                acc[j].z += xv * wv.z;
                acc[j].w += xv * wv.w;
            }
        }
        __syncthreads();
    }
    #pragma unroll
    for (int j = 0; j < 8; j++) {
        int row = m0 + ty * 8 + j;
        if (row < n) *(float4*)&g_h[row * 128 + tx * 4] = acc[j];
    }
}

// ---------------- Aggregation (warp per node, CSR) + fused BN stat partials ----------------
__global__ __launch_bounds__(256) void agg_kernel(const float* __restrict__ bias, int n) {
    __shared__ float red[8][256];
    int tid = threadIdx.x;
    int lane = tid & 31, wid = tid >> 5;
    float4 bv = *(const float4*)&bias[lane * 4];

    float ls0 = 0.f, ls1 = 0.f, ls2 = 0.f, ls3 = 0.f;
    float lq0 = 0.f, lq1 = 0.f, lq2 = 0.f, lq3 = 0.f;

    for (int node = blockIdx.x * 8 + wid; node < n; node += gridDim.x * 8) {
        int beg = g_rowptr[node];
        int end = g_rowptr[node + 1];
        float ax = 0.f, ay = 0.f, az = 0.f, aw = 0.f;
        int j = beg;
        for (; j + 1 < end; j += 2) {
            int   c0 = g_cols[j],     c1 = g_cols[j + 1];
            float w0 = g_wts[j],      w1 = g_wts[j + 1];
            float4 h0 = *(const float4*)&g_h[c0 * 128 + lane * 4];
            float4 h1 = *(const float4*)&g_h[c1 * 128 + lane * 4];
            ax += w0 * h0.x + w1 * h1.x;
            ay += w0 * h0.y + w1 * h1.y;
            az += w0 * h0.z + w1 * h1.z;
            aw += w0 * h0.w + w1 * h1.w;
        }
        if (j < end) {
            int c0 = g_cols[j];
            float w0 = g_wts[j];
            float4 h0 = *(const float4*)&g_h[c0 * 128 + lane * 4];
            ax += w0 * h0.x; ay += w0 * h0.y; az += w0 * h0.z; aw += w0 * h0.w;
        }
        float sn = g_dis[node]; sn = sn * sn;
        float4 hs = *(const float4*)&g_h[node * 128 + lane * 4];
        ax += sn * hs.x + bv.x;
        ay += sn * hs.y + bv.y;
        az += sn * hs.z + bv.z;
        aw += sn * hs.w + bv.w;
        float4 o = make_float4(ax, ay, az, aw);
        *(float4*)&g_agg[node * 128 + lane * 4] = o;

        ls0 += ax; ls1 += ay; ls2 += az; ls3 += aw;
        lq0 += ax * ax; lq1 += ay * ay; lq2 += az * az; lq3 += aw * aw;
    }

    red[wid][lane * 4 + 0] = ls0;
    red[wid][lane * 4 + 1] = ls1;
    red[wid][lane * 4 + 2] = ls2;
    red[wid][lane * 4 + 3] = ls3;
    red[wid][128 + lane * 4 + 0] = lq0;
    red[wid][128 + lane * 4 + 1] = lq1;
    red[wid][128 + lane * 4 + 2] = lq2;
    red[wid][128 + lane * 4 + 3] = lq3;
    __syncthreads();
    float tot = 0.f;
    #pragma unroll
    for (int w = 0; w < 8; w++) tot += red[w][tid];
    atomicAdd(&g_stats[tid], tot);
}

// ---------------- BN finalize: fold gamma/beta/mean/istd into scale/shift, reset stats ----------------
__global__ void finalize_kernel(const float* __restrict__ gamma, const float* __restrict__ beta,
                                float invn) {
    int c = threadIdx.x;  // 128 threads
    float s  = g_stats[c];
    float sq = g_stats[128 + c];
    float mean = s * invn;
    float var  = sq * invn - mean * mean;
    float istd = rsqrtf(var + 1e-5f);
    float sc = gamma[c] * istd;
    g_scale[c] = sc;
    g_shift[c] = beta[c] - mean * sc;
    g_stats[c] = 0.f;
    g_stats[128 + c] = 0.f;
}

// ---------------- Elementwise: y = agg*scale + shift; relu; residual; write ----------------
__global__ __launch_bounds__(256) void elem_kernel(float* __restrict__ out_ext,
                                                   int n4, int relu, int residual,
                                                   int out_to_global) {
    int idx = blockIdx.x * blockDim.x + threadIdx.x;
    if (idx >= n4) return;
    int c4 = idx & 31;
    float4 sc = ((const float4*)g_scale)[c4];
    float4 sh = ((const float4*)g_shift)[c4];
    float4 a  = ((const float4*)g_agg)[idx];
    float4 y;
    y.x = a.x * sc.x + sh.x;
    y.y = a.y * sc.y + sh.y;
    y.z = a.z * sc.z + sh.z;
    y.w = a.w * sc.w + sh.w;
    if (relu) {
        y.x = fmaxf(y.x, 0.f); y.y = fmaxf(y.y, 0.f);
        y.z = fmaxf(y.z, 0.f); y.w = fmaxf(y.w, 0.f);
    }
    if (residual) {
        float4 r = ((const float4*)g_x)[idx];
        y.x += r.x; y.y += r.y; y.z += r.z; y.w += r.w;
    }
    if (out_to_global) ((float4*)g_x)[idx] = y;
    else               ((float4*)out_ext)[idx] = y;
}

// ---------------- launch ----------------
extern "C" void kernel_launch(void* const* d_in, const int* in_sizes, int n_in,
                              void* d_out, int out_size) {
    const float* x      = (const float*)d_in[0];
    const int*   ei     = (const int*)d_in[1];
    const float* Ws     = (const float*)d_in[2];
    const float* bs     = (const float*)d_in[3];
    const float* gammas = (const float*)d_in[4];
    const float* betas  = (const float*)d_in[5];

    int n = in_sizes[0] / DD;   // 50000
    int e = in_sizes[1] / 2;    // 800000
    const int* src = ei;
    const int* dst = ei + e;

    // CSR build (once per launch; graph-capturable, no allocations)
    zero_kernel<<<196, 256>>>(n);
    degree_kernel<<<(e + 255) / 256, 256>>>(dst, e);
    scan_kernel<<<1, 1024>>>(n);
    fill_kernel<<<(e + 255) / 256, 256>>>(src, dst, e);

    float invn = 1.0f / (float)n;
    int n4 = n * (DD / 4);
    int gemm_grid = (n + 63) / 64;
    int agg_grid = 1184;  // 8 blocks/SM x 148

    for (int l = 0; l < 3; l++) {
        gemm_kernel<<<gemm_grid, 256>>>(x, Ws + l * DD * DD, n, l > 0 ? 1 : 0);
        agg_kernel<<<agg_grid, 256>>>(bs + l * DD, n);
        finalize_kernel<<<1, 128>>>(gammas + l * DD, betas + l * DD, invn);
        int relu = (l < 2) ? 1 : 0;
        int residual = (l > 0) ? 1 : 0;
        int out_to_global = (l < 2) ? 1 : 0;
        elem_kernel<<<(n4 + 255) / 256, 256>>>((float*)d_out, n4, relu, residual, out_to_global);
    }
}